// round 8
// baseline (speedup 1.0000x reference)
#include <cuda_runtime.h>
#include <cuda_bf16.h>
#include <cstdint>

// Segmented layer norm, chunk-pipelined TMA-cached single-read version.
// inputs: [0] input f32 [N,64], [1] offsets i32 [S] (cumulative ends),
//         [2] weight f32 [64], [3] bias f32 [64] ; output f32 [N,64]
//
// One CTA per segment (S=8192). The segment (<=400 rows, 100KB) is streamed
// HBM->smem with cp.async.bulk in 128-row (32KB) chunks on separate mbarriers,
// all issued up front; pass 1 consumes chunk c as soon as it lands, so only
// the first chunk's latency is exposed. Pass 2 normalizes from smem.
// DRAM traffic = 512MB read + 512MB write exactly. TPB=512, 2 CTAs/SM.

#define TPB 512
#define CAP_ROWS 400              // 400 rows * 256B = 102400 B dynamic smem
#define CHUNK_ROWS 128            // 32KB per TMA chunk
#define MAX_CHUNKS 4              // ceil(400/128)
#define EPS 1e-5f

extern __shared__ float4 s_cache[];   // [CAP_ROWS * 16]

__device__ __forceinline__ uint32_t smem_u32(const void* p) {
    uint32_t a;
    asm("{ .reg .u64 t; cvta.to.shared.u64 t, %1; cvt.u32.u64 %0, t; }"
        : "=r"(a) : "l"(p));
    return a;
}

__device__ __forceinline__ void mbar_wait(uint32_t mbar) {
    uint32_t done = 0;
    while (!done) {
        asm volatile(
            "{ .reg .pred p;\n"
            "  mbarrier.try_wait.parity.acquire.cta.shared::cta.b64 p, [%1], %2, 0x989680;\n"
            "  selp.b32 %0, 1, 0, p; }"
            : "=r"(done) : "r"(mbar), "r"(0u) : "memory");
    }
}

__global__ __launch_bounds__(TPB, 2) void seg_ln_kernel(
    const float* __restrict__ x,
    const int*   __restrict__ offsets,
    const float* __restrict__ weight,
    const float* __restrict__ bias,
    float*       __restrict__ out)
{
    const int s = blockIdx.x;
    const int t = threadIdx.x;

    const int start = (s == 0) ? 0 : offsets[s - 1];
    const int end   = offsets[s];
    const int len   = end - start;
    const int crows = (len < CAP_ROWS) ? len : CAP_ROWS;
    const int n_chunks = (crows + CHUNK_ROWS - 1) / CHUNK_ROWS;

    __shared__ float sm_sum[16][16][4];   // [warp][chunk16][component]
    __shared__ float sm_sq [16][16][4];
    __shared__ float sm_a[64];
    __shared__ float sm_b[64];
    __shared__ uint64_t sm_mbar[MAX_CHUNKS];

    const int chunk = t & 15;     // float4 chunk within the 64-float row
    const int rgrp  = t >> 4;     // row offset within a 32-row group (0..31)
    const int lane  = t & 31;
    const int warp  = t >> 5;

    const float4* __restrict__ xv = reinterpret_cast<const float4*>(x);
    float4*       __restrict__ ov = reinterpret_cast<float4*>(out);

    const uint32_t mbar0 = smem_u32(&sm_mbar[0]);
    const uint32_t cache_base = smem_u32(s_cache);

    // ---- Init barriers, then issue ALL chunk copies up front ----
    if (t == 0) {
        #pragma unroll
        for (int c = 0; c < MAX_CHUNKS; ++c)
            asm volatile("mbarrier.init.shared.b64 [%0], %1;"
                         :: "r"(mbar0 + 8u * c), "r"(1) : "memory");
    }
    __syncthreads();
    if (t == 0) {
        for (int c = 0; c < n_chunks; ++c) {
            const int row0 = c * CHUNK_ROWS;
            const int rows = ((crows - row0) < CHUNK_ROWS) ? (crows - row0) : CHUNK_ROWS;
            const uint32_t bytes = (uint32_t)rows * 256u;
            const uint32_t mb = mbar0 + 8u * c;
            asm volatile("mbarrier.arrive.expect_tx.shared.b64 _, [%0], %1;"
                         :: "r"(mb), "r"(bytes) : "memory");
            asm volatile(
                "cp.async.bulk.shared::cluster.global.mbarrier::complete_tx::bytes "
                "[%0], [%1], %2, [%3];"
                :: "r"(cache_base + (uint32_t)row0 * 256u),
                   "l"(xv + (size_t)(start + row0) * 16), "r"(bytes),
                   "r"(mb) : "memory");
        }
    }

    // ---- Pass 1: consume chunks as they land; per-feature sum / sumsq ----
    float4 acc  = make_float4(0.f, 0.f, 0.f, 0.f);
    float4 accq = make_float4(0.f, 0.f, 0.f, 0.f);

    for (int c = 0; c < n_chunks; ++c) {
        mbar_wait(mbar0 + 8u * c);
        const int row0 = c * CHUNK_ROWS;
        const int rend = ((crows - row0) < CHUNK_ROWS) ? crows : row0 + CHUNK_ROWS;
        int r = row0 + rgrp;
        for (; r + 32 < rend; r += 64) {
            float4 v0 = s_cache[(r     ) * 16 + chunk];
            float4 v1 = s_cache[(r + 32) * 16 + chunk];
            acc.x += v0.x + v1.x; acc.y += v0.y + v1.y;
            acc.z += v0.z + v1.z; acc.w += v0.w + v1.w;
            accq.x = fmaf(v0.x, v0.x, fmaf(v1.x, v1.x, accq.x));
            accq.y = fmaf(v0.y, v0.y, fmaf(v1.y, v1.y, accq.y));
            accq.z = fmaf(v0.z, v0.z, fmaf(v1.z, v1.z, accq.z));
            accq.w = fmaf(v0.w, v0.w, fmaf(v1.w, v1.w, accq.w));
        }
        if (r < rend) {
            float4 v = s_cache[r * 16 + chunk];
            acc.x += v.x; acc.y += v.y; acc.z += v.z; acc.w += v.w;
            accq.x = fmaf(v.x, v.x, accq.x); accq.y = fmaf(v.y, v.y, accq.y);
            accq.z = fmaf(v.z, v.z, accq.z); accq.w = fmaf(v.w, v.w, accq.w);
        }
    }
    // Overflow tail (essentially never taken; correctness guard)
    for (int rr = CAP_ROWS + rgrp; rr < len; rr += 32) {
        float4 v = __ldg(&xv[(size_t)(start + rr) * 16 + chunk]);
        acc.x += v.x; acc.y += v.y; acc.z += v.z; acc.w += v.w;
        accq.x = fmaf(v.x, v.x, accq.x); accq.y = fmaf(v.y, v.y, accq.y);
        accq.z = fmaf(v.z, v.z, accq.z); accq.w = fmaf(v.w, v.w, accq.w);
    }

    // ---- Warp fold: lanes L and L^16 share a chunk, differ in rgrp ----
    acc.x  += __shfl_xor_sync(0xffffffffu, acc.x,  16);
    acc.y  += __shfl_xor_sync(0xffffffffu, acc.y,  16);
    acc.z  += __shfl_xor_sync(0xffffffffu, acc.z,  16);
    acc.w  += __shfl_xor_sync(0xffffffffu, acc.w,  16);
    accq.x += __shfl_xor_sync(0xffffffffu, accq.x, 16);
    accq.y += __shfl_xor_sync(0xffffffffu, accq.y, 16);
    accq.z += __shfl_xor_sync(0xffffffffu, accq.z, 16);
    accq.w += __shfl_xor_sync(0xffffffffu, accq.w, 16);
    if (lane < 16) {
        sm_sum[warp][chunk][0] = acc.x;  sm_sum[warp][chunk][1] = acc.y;
        sm_sum[warp][chunk][2] = acc.z;  sm_sum[warp][chunk][3] = acc.w;
        sm_sq [warp][chunk][0] = accq.x; sm_sq [warp][chunk][1] = accq.y;
        sm_sq [warp][chunk][2] = accq.z; sm_sq [warp][chunk][3] = accq.w;
    }
    __syncthreads();

    // ---- Final reduce over 16 warps; fold scale/shift per feature ----
    if (t < 64) {
        const int c = t >> 2;
        const int k = t & 3;
        float fsum = 0.f, fsq = 0.f;
        #pragma unroll
        for (int w = 0; w < 16; ++w) {
            fsum += sm_sum[w][c][k];
            fsq  += sm_sq [w][c][k];
        }
        const float inv  = 1.0f / (float)len;
        const float mean = fsum * inv;
        float var = fsq * inv - mean * mean;
        var = fmaxf(var, 0.0f);
        const float rstd = rsqrtf(var + EPS);
        const float a = weight[t] * rstd;
        sm_a[t] = a;
        sm_b[t] = bias[t] - mean * a;
    }
    __syncthreads();

    const float4 av = reinterpret_cast<const float4*>(sm_a)[chunk];
    const float4 bv = reinterpret_cast<const float4*>(sm_b)[chunk];

    // ---- Pass 2: normalize from smem, store ----
    int r = rgrp;
    for (; r + 32 < crows; r += 64) {
        float4 v0 = s_cache[(r     ) * 16 + chunk];
        float4 v1 = s_cache[(r + 32) * 16 + chunk];
        float4 w0, w1;
        w0.x = fmaf(v0.x, av.x, bv.x); w0.y = fmaf(v0.y, av.y, bv.y);
        w0.z = fmaf(v0.z, av.z, bv.z); w0.w = fmaf(v0.w, av.w, bv.w);
        w1.x = fmaf(v1.x, av.x, bv.x); w1.y = fmaf(v1.y, av.y, bv.y);
        w1.z = fmaf(v1.z, av.z, bv.z); w1.w = fmaf(v1.w, av.w, bv.w);
        ov[(size_t)(start + r     ) * 16 + chunk] = w0;
        ov[(size_t)(start + r + 32) * 16 + chunk] = w1;
    }
    if (r < crows) {
        float4 v = s_cache[r * 16 + chunk];
        float4 w;
        w.x = fmaf(v.x, av.x, bv.x); w.y = fmaf(v.y, av.y, bv.y);
        w.z = fmaf(v.z, av.z, bv.z); w.w = fmaf(v.w, av.w, bv.w);
        ov[(size_t)(start + r) * 16 + chunk] = w;
    }
    // Overflow tail (essentially never taken)
    for (int rr = CAP_ROWS + rgrp; rr < len; rr += 32) {
        float4 v = __ldg(&xv[(size_t)(start + rr) * 16 + chunk]);
        float4 w;
        w.x = fmaf(v.x, av.x, bv.x); w.y = fmaf(v.y, av.y, bv.y);
        w.z = fmaf(v.z, av.z, bv.z); w.w = fmaf(v.w, av.w, bv.w);
        ov[(size_t)(start + rr) * 16 + chunk] = w;
    }
}

extern "C" void kernel_launch(void* const* d_in, const int* in_sizes, int n_in,
                              void* d_out, int out_size)
{
    const float* x       = (const float*)d_in[0];
    const int*   offsets = (const int*)  d_in[1];
    const float* weight  = (const float*)d_in[2];
    const float* bias    = (const float*)d_in[3];
    float*       out     = (float*)d_out;

    const int S = in_sizes[1];
    const int dyn_smem = CAP_ROWS * 16 * sizeof(float4);  // 102400 B

    cudaFuncSetAttribute(seg_ln_kernel,
                         cudaFuncAttributeMaxDynamicSharedMemorySize, dyn_smem);

    seg_ln_kernel<<<S, TPB, dyn_smem>>>(x, offsets, weight, bias, out);
}

// round 9
// speedup vs baseline: 1.0605x; 1.0605x over previous
#include <cuda_runtime.h>
#include <cuda_bf16.h>
#include <cstdint>

// Segmented layer norm, TMA-cached single-read, 3 CTAs/SM version.
// inputs: [0] input f32 [N,64], [1] offsets i32 [S] (cumulative ends),
//         [2] weight f32 [64], [3] bias f32 [64] ; output f32 [N,64]
//
// One CTA per segment (S=8192). One cp.async.bulk per CTA streams the segment
// (<=280 rows = 70KB) HBM->smem via mbarrier. Pass 1: per-feature sum/sumsq
// from smem, lane-fold + smem atomicAdd reduction (tiny static smem so THREE
// CTAs fit per SM for deep TMA/compute overlap). Pass 2 normalizes from smem.
// Rare >280-row overflow rows go through an LDG fallback path.
// DRAM traffic ~= 512MB read + 512MB write. TPB=384, 3 CTAs/SM (36 warps).

#define TPB 384
#define CAP_ROWS 280              // 280 rows * 256B = 71680 B dynamic smem
#define EPS 1e-5f

extern __shared__ float4 s_cache[];   // [CAP_ROWS * 16]

__device__ __forceinline__ uint32_t smem_u32(const void* p) {
    uint32_t a;
    asm("{ .reg .u64 t; cvta.to.shared.u64 t, %1; cvt.u32.u64 %0, t; }"
        : "=r"(a) : "l"(p));
    return a;
}

__global__ __launch_bounds__(TPB, 3) void seg_ln_kernel(
    const float* __restrict__ x,
    const int*   __restrict__ offsets,
    const float* __restrict__ weight,
    const float* __restrict__ bias,
    float*       __restrict__ out)
{
    const int s = blockIdx.x;
    const int t = threadIdx.x;

    const int start = (s == 0) ? 0 : offsets[s - 1];
    const int end   = offsets[s];
    const int len   = end - start;
    const int crows = (len < CAP_ROWS) ? len : CAP_ROWS;

    __shared__ float sm_sum[64];
    __shared__ float sm_sq [64];
    __shared__ float sm_a[64];
    __shared__ float sm_b[64];
    __shared__ uint64_t sm_mbar;

    const int chunk = t & 15;     // float4 chunk within the 64-float row
    const int rgrp  = t >> 4;     // row offset within a 24-row group (0..23)
    const int lane  = t & 31;

    const float4* __restrict__ xv = reinterpret_cast<const float4*>(x);
    float4*       __restrict__ ov = reinterpret_cast<float4*>(out);

    const uint32_t mbar = smem_u32(&sm_mbar);
    const uint32_t cache_base = smem_u32(s_cache);
    const uint32_t bytes = (uint32_t)crows * 256u;

    // ---- Init: zero accumulators, init mbarrier ----
    if (t < 64) { sm_sum[t] = 0.f; sm_sq[t] = 0.f; }
    if (t == 0) {
        asm volatile("mbarrier.init.shared.b64 [%0], %1;"
                     :: "r"(mbar), "r"(1) : "memory");
    }
    __syncthreads();

    // ---- Issue one bulk async copy for the whole cached segment ----
    if (t == 0) {
        asm volatile("mbarrier.arrive.expect_tx.shared.b64 _, [%0], %1;"
                     :: "r"(mbar), "r"(bytes) : "memory");
        asm volatile(
            "cp.async.bulk.shared::cluster.global.mbarrier::complete_tx::bytes "
            "[%0], [%1], %2, [%3];"
            :: "r"(cache_base), "l"(xv + (size_t)start * 16), "r"(bytes),
               "r"(mbar) : "memory");
    }

    // ---- Wait for the copy (acquire orders following LDS) ----
    {
        uint32_t done = 0;
        while (!done) {
            asm volatile(
                "{ .reg .pred p;\n"
                "  mbarrier.try_wait.parity.acquire.cta.shared::cta.b64 p, [%1], %2, 0x989680;\n"
                "  selp.b32 %0, 1, 0, p; }"
                : "=r"(done) : "r"(mbar), "r"(0u) : "memory");
        }
    }

    // ---- Pass 1: per-feature sum / sumsq from smem ----
    float4 acc  = make_float4(0.f, 0.f, 0.f, 0.f);
    float4 accq = make_float4(0.f, 0.f, 0.f, 0.f);

    int r = rgrp;
    for (; r + 24 < crows; r += 48) {
        float4 v0 = s_cache[(r     ) * 16 + chunk];
        float4 v1 = s_cache[(r + 24) * 16 + chunk];
        acc.x += v0.x + v1.x; acc.y += v0.y + v1.y;
        acc.z += v0.z + v1.z; acc.w += v0.w + v1.w;
        accq.x = fmaf(v0.x, v0.x, fmaf(v1.x, v1.x, accq.x));
        accq.y = fmaf(v0.y, v0.y, fmaf(v1.y, v1.y, accq.y));
        accq.z = fmaf(v0.z, v0.z, fmaf(v1.z, v1.z, accq.z));
        accq.w = fmaf(v0.w, v0.w, fmaf(v1.w, v1.w, accq.w));
    }
    if (r < crows) {
        float4 v = s_cache[r * 16 + chunk];
        acc.x += v.x; acc.y += v.y; acc.z += v.z; acc.w += v.w;
        accq.x = fmaf(v.x, v.x, accq.x); accq.y = fmaf(v.y, v.y, accq.y);
        accq.z = fmaf(v.z, v.z, accq.z); accq.w = fmaf(v.w, v.w, accq.w);
    }
    // Overflow tail (rare: ~7% of segments, a few rows; correctness guard)
    for (int rr = CAP_ROWS + rgrp; rr < len; rr += 24) {
        float4 v = __ldg(&xv[(size_t)(start + rr) * 16 + chunk]);
        acc.x += v.x; acc.y += v.y; acc.z += v.z; acc.w += v.w;
        accq.x = fmaf(v.x, v.x, accq.x); accq.y = fmaf(v.y, v.y, accq.y);
        accq.z = fmaf(v.z, v.z, accq.z); accq.w = fmaf(v.w, v.w, accq.w);
    }

    // ---- Warp fold (lanes L, L^16 share chunk), then smem atomic reduce ----
    acc.x  += __shfl_xor_sync(0xffffffffu, acc.x,  16);
    acc.y  += __shfl_xor_sync(0xffffffffu, acc.y,  16);
    acc.z  += __shfl_xor_sync(0xffffffffu, acc.z,  16);
    acc.w  += __shfl_xor_sync(0xffffffffu, acc.w,  16);
    accq.x += __shfl_xor_sync(0xffffffffu, accq.x, 16);
    accq.y += __shfl_xor_sync(0xffffffffu, accq.y, 16);
    accq.z += __shfl_xor_sync(0xffffffffu, accq.z, 16);
    accq.w += __shfl_xor_sync(0xffffffffu, accq.w, 16);
    if (lane < 16) {
        atomicAdd(&sm_sum[chunk * 4 + 0], acc.x);
        atomicAdd(&sm_sum[chunk * 4 + 1], acc.y);
        atomicAdd(&sm_sum[chunk * 4 + 2], acc.z);
        atomicAdd(&sm_sum[chunk * 4 + 3], acc.w);
        atomicAdd(&sm_sq [chunk * 4 + 0], accq.x);
        atomicAdd(&sm_sq [chunk * 4 + 1], accq.y);
        atomicAdd(&sm_sq [chunk * 4 + 2], accq.z);
        atomicAdd(&sm_sq [chunk * 4 + 3], accq.w);
    }
    __syncthreads();

    // ---- Fold scale/shift per feature ----
    if (t < 64) {
        const float inv  = 1.0f / (float)len;
        const float mean = sm_sum[t] * inv;
        float var = sm_sq[t] * inv - mean * mean;
        var = fmaxf(var, 0.0f);
        const float rstd = rsqrtf(var + EPS);
        const float a = weight[t] * rstd;
        sm_a[t] = a;
        sm_b[t] = bias[t] - mean * a;
    }
    __syncthreads();

    const float4 av = reinterpret_cast<const float4*>(sm_a)[chunk];
    const float4 bv = reinterpret_cast<const float4*>(sm_b)[chunk];

    // ---- Pass 2: normalize from smem, store ----
    r = rgrp;
    for (; r + 24 < crows; r += 48) {
        float4 v0 = s_cache[(r     ) * 16 + chunk];
        float4 v1 = s_cache[(r + 24) * 16 + chunk];
        float4 w0, w1;
        w0.x = fmaf(v0.x, av.x, bv.x); w0.y = fmaf(v0.y, av.y, bv.y);
        w0.z = fmaf(v0.z, av.z, bv.z); w0.w = fmaf(v0.w, av.w, bv.w);
        w1.x = fmaf(v1.x, av.x, bv.x); w1.y = fmaf(v1.y, av.y, bv.y);
        w1.z = fmaf(v1.z, av.z, bv.z); w1.w = fmaf(v1.w, av.w, bv.w);
        ov[(size_t)(start + r     ) * 16 + chunk] = w0;
        ov[(size_t)(start + r + 24) * 16 + chunk] = w1;
    }
    if (r < crows) {
        float4 v = s_cache[r * 16 + chunk];
        float4 w;
        w.x = fmaf(v.x, av.x, bv.x); w.y = fmaf(v.y, av.y, bv.y);
        w.z = fmaf(v.z, av.z, bv.z); w.w = fmaf(v.w, av.w, bv.w);
        ov[(size_t)(start + r) * 16 + chunk] = w;
    }
    // Overflow tail (rare)
    for (int rr = CAP_ROWS + rgrp; rr < len; rr += 24) {
        float4 v = __ldg(&xv[(size_t)(start + rr) * 16 + chunk]);
        float4 w;
        w.x = fmaf(v.x, av.x, bv.x); w.y = fmaf(v.y, av.y, bv.y);
        w.z = fmaf(v.z, av.z, bv.z); w.w = fmaf(v.w, av.w, bv.w);
        ov[(size_t)(start + rr) * 16 + chunk] = w;
    }
}

extern "C" void kernel_launch(void* const* d_in, const int* in_sizes, int n_in,
                              void* d_out, int out_size)
{
    const float* x       = (const float*)d_in[0];
    const int*   offsets = (const int*)  d_in[1];
    const float* weight  = (const float*)d_in[2];
    const float* bias    = (const float*)d_in[3];
    float*       out     = (float*)d_out;

    const int S = in_sizes[1];
    const int dyn_smem = CAP_ROWS * 16 * sizeof(float4);  // 71680 B

    cudaFuncSetAttribute(seg_ln_kernel,
                         cudaFuncAttributeMaxDynamicSharedMemorySize, dyn_smem);

    seg_ln_kernel<<<S, TPB, dyn_smem>>>(x, offsets, weight, bias, out);
}